// round 8
// baseline (speedup 1.0000x reference)
#include <cuda_runtime.h>
#include <math.h>
#include <stdint.h>

#define NB      262144
#define TT      80
#define NSTEP   30
#define TILE    384               // rows per block per tile (12 warps)
#define NTILES  ((NB + TILE - 1) / TILE)   // 683 (last tile partial: 256 rows)
#define TS      30                // stage exactly elements 50..79; 2-way LDS conflict
#define DTC     0.1f
#define GRID    152               // persistent: 1 CTA per SM on GB300
#define YV_OFF  (TILE * TS)       // V offset within a buffer (floats)
#define BUFELEMS (2 * TILE * TS)  // Y + V for one buffer
#define SMEM_BYTES (2 * BUFELEMS * sizeof(float))   // 184320 B

__device__ __forceinline__ void cpa8(uint32_t dst, const float* src) {
    asm volatile("cp.async.ca.shared.global [%0], [%1], 8;" :: "r"(dst), "l"(src));
}

__global__ __launch_bounds__(TILE, 1)
void traj_kernel(const float* __restrict__ params,
                 const float* __restrict__ sv_v,
                 const float* __restrict__ hh,
                 const float* __restrict__ dvv,
                 const float* __restrict__ svY,
                 const float* __restrict__ lvY,
                 const float* __restrict__ lvv,
                 float* __restrict__ out)
{
    extern __shared__ float smem[];      // [2][{Y,V}][TILE][TS]
    const int tid   = threadIdx.x;
    const int wid   = tid >> 5;
    const int lane  = tid & 31;
    const int wrow0 = wid * 32;
    const uint32_t smem_u32 = (uint32_t)__cvta_generic_to_shared(smem);

    // Params: broadcast, L1-resident.
    const float s0  = __ldg(params + 0);
    const float Thw = __ldg(params + 1);
    const float pa  = __ldg(params + 2);
    const float pb  = __ldg(params + 3);
    const float v0  = __ldg(params + 4);
    const float inv_c2 = 1.0f / (2.0f * sqrtf(pa * pb));
    const float inv_v0 = 1.0f / v0;

    // Warp-staging lane mapping: 30 active lanes cover 2 rows x 15 8B-chunks.
    const int srow = (lane >= 15) ? 1 : 0;       // sub-row within pair
    const int sc   = lane - (srow ? 15 : 0);     // chunk 0..14
    const bool sact = (lane < 30);

    int t   = blockIdx.x;
    int buf = 0;
    float nv = 0.f, ngap = 0.f, ndvl = 0.f, ny = 0.f;

    // ---- Prologue: async-stage tile t into buffer 0, prefetch its scalars. ----
    {
        const int r0 = t * TILE;
        if (sact) {
            #pragma unroll
            for (int k = 0; k < 16; ++k) {
                int row  = wrow0 + 2 * k + srow;
                int grow = min(r0 + row, NB - 1);          // clamp partial tile
                size_t g = (size_t)grow * TT + 50 + sc * 2;
                uint32_t dY = smem_u32 + (uint32_t)(row * TS + sc * 2) * 4u;
                cpa8(dY, lvY + g);
                cpa8(dY + (uint32_t)YV_OFF * 4u, lvv + g);
            }
        }
        asm volatile("cp.async.commit_group;");
        int gr = r0 + tid;
        if (gr < NB) {
            size_t sb = (size_t)gr * TT + 49;
            nv   = __ldg(sv_v + sb);
            ngap = __ldg(hh   + sb);
            ndvl = __ldg(dvv  + sb);
            ny   = __ldg(svY  + sb);
        }
    }

    while (t < NTILES) {
        const int tn = t + (int)gridDim.x;
        float v = nv, gap = ngap, dvl = ndvl, y = ny;

        if (tn < NTILES) {
            // ---- Issue next tile's loads into the other buffer. ----
            const int r0n = tn * TILE;
            const uint32_t ob = (uint32_t)((buf ^ 1) * BUFELEMS) * 4u;
            if (sact) {
                #pragma unroll
                for (int k = 0; k < 16; ++k) {
                    int row  = wrow0 + 2 * k + srow;
                    int grow = min(r0n + row, NB - 1);
                    size_t g = (size_t)grow * TT + 50 + sc * 2;
                    uint32_t dY = smem_u32 + ob + (uint32_t)(row * TS + sc * 2) * 4u;
                    cpa8(dY, lvY + g);
                    cpa8(dY + (uint32_t)YV_OFF * 4u, lvv + g);
                }
            }
            asm volatile("cp.async.commit_group;");
            int gr = r0n + tid;
            if (gr < NB) {
                size_t sb = (size_t)gr * TT + 49;
                nv   = __ldg(sv_v + sb);
                ngap = __ldg(hh   + sb);
                ndvl = __ldg(dvv  + sb);
                ny   = __ldg(svY  + sb);
            }
            asm volatile("cp.async.wait_group 1;");  // tile t's group done; tn in flight
        } else {
            asm volatile("cp.async.wait_group 0;");
        }
        __syncwarp();

        // ---- Compute this warp's 32 rows from buffer `buf`. ----
        float* bY  = smem + buf * BUFELEMS;
        float* myY = bY + tid * TS;              // element 50 = index 0
        const float* myV = myY + YV_OFF;

        #pragma unroll
        for (int i = 0; i < NSTEP; ++i) {
            // s_star = s0 + max(v*Thw + v*dv/(2*sqrt(a*b)), 0)  (NaN-propagating max)
            float tt     = v * Thw + (v * dvl) * inv_c2;
            float relu   = !(tt <= 0.0f) ? tt : 0.0f;
            float s_star = s0 + relu;

            float rv  = v * inv_v0;
            float rv2 = rv * rv;
            float rs  = __fdividef(s_star, gap);
            float a_calc = pa * (1.0f - rv2 * rv2 - rs * rs);

            float v2  = v + a_calc * DTC;
            // where(v2 <= 0, -v/DT, a_calc); 1/0.1f rounds to exactly 10.0f
            float a_t = (v2 <= 0.0f) ? (-v * 10.0f) : a_calc;

            v   = v + a_t * DTC;
            dvl = v - myV[i];
            y   = y + v * DTC;
            gap = myY[i] - y;     // last read of lv_Y slot i ...
            myY[i] = y;           // ... reuse it to stage the output in place
        }
        __syncwarp();

        // ---- Warp-private coalesced writeback: 960 contiguous floats. ----
        const size_t obase = ((size_t)t * TILE + wrow0) * NSTEP;
        const float* wO = bY + wrow0 * TS;
        #pragma unroll
        for (int k = 0; k < NSTEP; ++k) {
            int idx = k * 32 + lane;
            size_t o = obase + idx;
            if (o < (size_t)NB * NSTEP) {
                int row = idx / NSTEP;
                int col = idx - row * NSTEP;
                out[o] = wO[row * TS + col];
            }
        }
        __syncwarp();   // SMEM reads done before this buffer is refilled

        buf ^= 1;
        t = tn;
    }
}

extern "C" void kernel_launch(void* const* d_in, const int* in_sizes, int n_in,
                              void* d_out, int out_size) {
    const float* params = (const float*)d_in[0];
    const float* sv_v1  = (const float*)d_in[1];
    const float* h1     = (const float*)d_in[2];
    const float* dv1    = (const float*)d_in[3];
    const float* sv_Y1  = (const float*)d_in[4];
    const float* lvY    = (const float*)d_in[5];
    const float* lvv    = (const float*)d_in[6];
    float* out = (float*)d_out;

    cudaFuncSetAttribute(traj_kernel,
                         cudaFuncAttributeMaxDynamicSharedMemorySize,
                         (int)SMEM_BYTES);
    traj_kernel<<<GRID, TILE, SMEM_BYTES>>>(params, sv_v1, h1, dv1, sv_Y1,
                                            lvY, lvv, out);
}